// round 1
// baseline (speedup 1.0000x reference)
#include <cuda_runtime.h>
#include <math.h>
#include <float.h>

#define D 128
#define KCODES 1024
#define BM 64          // rows per CTA
#define BN 128         // codes per smem chunk
#define SCS 132        // padded row stride (floats) for code tile
#define TM 4           // rows per thread
#define TN 8           // codes per thread
#define NTH 256

__device__ float g_cnorm[KCODES];
__device__ int g_counts[KCODES];
__device__ unsigned long long g_sse;

__global__ void prep_kernel(const float* __restrict__ cb) {
    int t = blockIdx.x * blockDim.x + threadIdx.x;
    if (t < KCODES) {
        g_counts[t] = 0;
        const float* row = cb + (size_t)t * D;
        float s = 0.f;
        #pragma unroll 8
        for (int d = 0; d < D; ++d) s = fmaf(row[d], row[d], s);
        g_cnorm[t] = s;
        if (t == 0) g_sse = 0ull;
    }
}

__global__ __launch_bounds__(NTH) void vq_main(
        const float* __restrict__ x, const float* __restrict__ cb,
        float* __restrict__ out, int nrows) {
    extern __shared__ float smem[];
    float* sx   = smem;                   // BM*D
    float* sc   = sx + BM * D;            // BN*SCS
    float* sxn  = sc + BN * SCS;          // BM
    float* sbv  = sxn + BM;               // BM*16
    int*   sbi  = (int*)(sbv + BM * 16);  // BM*16
    int*   srid = sbi + BM * 16;          // BM

    const int tid = threadIdx.x;
    const int row0 = blockIdx.x * BM;

    // stage x tile: 64 consecutive rows = contiguous 32KB
    float4* sx4 = (float4*)sx;
    const float4* xg4 = (const float4*)(x + (size_t)row0 * D);
    #pragma unroll
    for (int i = tid; i < BM * D / 4; i += NTH) sx4[i] = xg4[i];
    __syncthreads();

    // per-row x norms
    if (tid < BM) {
        const float* r = sx + tid * D;
        float s = 0.f;
        #pragma unroll 8
        for (int d = 0; d < D; ++d) s = fmaf(r[d], r[d], s);
        sxn[tid] = s;
    }
    __syncthreads();

    const int ty = tid >> 4;   // 0..15 row group
    const int tx = tid & 15;   // 0..15 code group

    float xn[TM];
    #pragma unroll
    for (int i = 0; i < TM; ++i) xn[i] = sxn[ty * TM + i];

    float bestv[TM];
    int   besti[TM];
    #pragma unroll
    for (int i = 0; i < TM; ++i) { bestv[i] = FLT_MAX; besti[i] = 0; }

    for (int kc = 0; kc < KCODES; kc += BN) {
        // stage BN codes into padded smem rows
        const float4* cg4 = (const float4*)(cb + (size_t)kc * D);
        #pragma unroll
        for (int i = tid; i < BN * D / 4; i += NTH) {
            int k  = i >> 5;          // 32 float4 per code row
            int d4 = (i & 31) << 2;
            *(float4*)(sc + k * SCS + d4) = cg4[i];
        }
        __syncthreads();

        float acc[TM][TN];
        #pragma unroll
        for (int i = 0; i < TM; ++i)
            #pragma unroll
            for (int j = 0; j < TN; ++j) acc[i][j] = 0.f;

        #pragma unroll 4
        for (int d = 0; d < D; d += 4) {
            float4 xv[TM], cv[TN];
            #pragma unroll
            for (int i = 0; i < TM; ++i)
                xv[i] = *(const float4*)(sx + (ty * TM + i) * D + d);
            #pragma unroll
            for (int j = 0; j < TN; ++j)
                cv[j] = *(const float4*)(sc + (tx + 16 * j) * SCS + d);
            #pragma unroll
            for (int i = 0; i < TM; ++i)
                #pragma unroll
                for (int j = 0; j < TN; ++j) {
                    acc[i][j] = fmaf(xv[i].x, cv[j].x, acc[i][j]);
                    acc[i][j] = fmaf(xv[i].y, cv[j].y, acc[i][j]);
                    acc[i][j] = fmaf(xv[i].z, cv[j].z, acc[i][j]);
                    acc[i][j] = fmaf(xv[i].w, cv[j].w, acc[i][j]);
                }
        }

        // score + running argmin; k ascends in j, chunks ascend -> strict <
        // reproduces the reference tie-break (first index wins)
        #pragma unroll
        for (int j = 0; j < TN; ++j) {
            int k = kc + tx + 16 * j;
            float cn = g_cnorm[k];
            #pragma unroll
            for (int i = 0; i < TM; ++i) {
                float t = xn[i] + cn;                    // fl(x_norm + c_norm)
                float dist = fmaf(-2.0f, acc[i][j], t);  // == fl(t - 2*dot), 2*dot exact
                dist = fmaxf(dist, 0.0f);
                if (dist < bestv[i]) { bestv[i] = dist; besti[i] = k; }
            }
        }
        __syncthreads();
    }

    // cross-thread argmin reduction (lexicographic: value, then index)
    #pragma unroll
    for (int i = 0; i < TM; ++i) {
        sbv[(ty * TM + i) * 16 + tx] = bestv[i];
        sbi[(ty * TM + i) * 16 + tx] = besti[i];
    }
    __syncthreads();
    if (tid < BM) {
        float bv = sbv[tid * 16];
        int   bi = sbi[tid * 16];
        #pragma unroll
        for (int j = 1; j < 16; ++j) {
            float v = sbv[tid * 16 + j];
            int  ii = sbi[tid * 16 + j];
            if (v < bv || (v == bv && ii < bi)) { bv = v; bi = ii; }
        }
        srid[tid] = bi;
        atomicAdd(&g_counts[bi], 1);
    }
    __syncthreads();

    // output z_st = x + (z - x), accumulate sum((z-x)^2)
    float lsse = 0.f;
    float4* og4 = (float4*)(out + (size_t)row0 * D);
    #pragma unroll
    for (int i = tid; i < BM * D / 4; i += NTH) {
        int r = i >> 5;
        int idx = srid[r];
        float4 zz = *(const float4*)(cb + (size_t)idx * D + ((i & 31) << 2));
        float4 xx = sx4[i];
        float4 o;
        float t0 = zz.x - xx.x; o.x = xx.x + t0;
        float t1 = zz.y - xx.y; o.y = xx.y + t1;
        float t2 = zz.z - xx.z; o.z = xx.z + t2;
        float t3 = zz.w - xx.w; o.w = xx.w + t3;
        lsse = fmaf(t0, t0, lsse);
        lsse = fmaf(t1, t1, lsse);
        lsse = fmaf(t2, t2, lsse);
        lsse = fmaf(t3, t3, lsse);
        og4[i] = o;
    }

    // deterministic fixed-point SSE accumulation
    #pragma unroll
    for (int off = 16; off; off >>= 1)
        lsse += __shfl_down_sync(0xffffffffu, lsse, off);
    __shared__ float swr[NTH / 32];
    int lane = tid & 31, wid = tid >> 5;
    if (lane == 0) swr[wid] = lsse;
    __syncthreads();
    if (tid == 0) {
        float s = 0.f;
        #pragma unroll
        for (int w = 0; w < NTH / 32; ++w) s += swr[w];
        unsigned long long fx = (unsigned long long)((double)s * 1048576.0 + 0.5);
        atomicAdd(&g_sse, fx);
    }
}

__global__ void finalize_kernel(float* __restrict__ out, int ntot, int nrows) {
    __shared__ float red[32];
    int t = threadIdx.x;
    float p = (float)g_counts[t] / (float)nrows;
    float term = p * logf(p + 1e-10f);
    #pragma unroll
    for (int off = 16; off; off >>= 1)
        term += __shfl_down_sync(0xffffffffu, term, off);
    if ((t & 31) == 0) red[t >> 5] = term;
    __syncthreads();
    if (t < 32) {
        float v = red[t];
        #pragma unroll
        for (int off = 16; off; off >>= 1)
            v += __shfl_down_sync(0xffffffffu, v, off);
        if (t == 0) {
            float sse = (float)((double)g_sse * (1.0 / 1048576.0));
            float loss = sse / (float)ntot;
            out[ntot]     = loss;        // quantization_loss
            out[ntot + 1] = loss;        // commitment_loss (same forward value)
            out[ntot + 2] = expf(-v);    // perplexity
        }
    }
}

extern "C" void kernel_launch(void* const* d_in, const int* in_sizes, int n_in,
                              void* d_out, int out_size) {
    const float* x  = (const float*)d_in[0];
    const float* cb = (const float*)d_in[1];
    float* out = (float*)d_out;
    int ntot  = in_sizes[0];
    int nrows = ntot / D;

    size_t smem_bytes = (size_t)(BM * D + BN * SCS + BM + BM * 16 + BM * 16 + BM)
                        * sizeof(float);
    cudaFuncSetAttribute(vq_main, cudaFuncAttributeMaxDynamicSharedMemorySize,
                         (int)smem_bytes);

    prep_kernel<<<1, KCODES>>>(cb);
    vq_main<<<nrows / BM, NTH, smem_bytes>>>(x, cb, out, nrows);
    finalize_kernel<<<1, KCODES>>>(out, ntot, nrows);
}